// round 9
// baseline (speedup 1.0000x reference)
#include <cuda_runtime.h>
#include <math.h>

#define NRAYS   16384
#define NSAMP   128
#define TMASK   ((1u << 19) - 1u)

// Direct libdevice declarations (immune to fast-math macro substitution).
extern "C" {
__device__ float  __nv_expf(float);
__device__ float  __nv_logf(float);
__device__ double __nv_exp(double);
}

// shared-memory weight offsets (in floats)
#define OFF_WS0 0        // 32x64
#define OFF_WS1 2048     // 64x64
#define OFF_WS2 6144     // 64x16
#define OFF_WC0 7168     // 31x64
#define OFF_WC1 9152     // 64x64
#define OFF_WC2 13248    // 64x64
#define OFF_WC3 17344    // 64x3
#define WTOT    17536

#define SMEM_FLOATS (WTOT + 128 + 128 + 32)
#define SMEM_BYTES  (SMEM_FLOATS * 4)

// Confirmed-correct resolutions (R8 falsified the flipped table).
__constant__ float c_res[16] = {16.f, 20.f, 25.f, 32.f, 40.f, 50.f, 64.f, 80.f,
                                101.f, 128.f, 161.f, 203.f, 256.f, 322.f, 406.f, 512.f};

__device__ __forceinline__ float block_reduce_128(float v, float* sbuf) {
    #pragma unroll
    for (int o = 16; o > 0; o >>= 1) v += __shfl_down_sync(0xffffffffu, v, o);
    int tid = threadIdx.x;
    __syncthreads();                 // protect sbuf from previous use
    if ((tid & 31) == 0) sbuf[tid >> 5] = v;
    __syncthreads();
    return (sbuf[0] + sbuf[1]) + (sbuf[2] + sbuf[3]);
}

__global__ void __launch_bounds__(128)
nerf_fused(const float* __restrict__ rays,
           const float* __restrict__ tables,
           const float* __restrict__ ws0, const float* __restrict__ ws1,
           const float* __restrict__ ws2,
           const float* __restrict__ wc0, const float* __restrict__ wc1,
           const float* __restrict__ wc2, const float* __restrict__ wc3,
           float* __restrict__ out)
{
    extern __shared__ float sm[];
    float* W       = sm;
    float* s_alpha = sm + WTOT;        // 128
    float* s_w     = s_alpha + 128;    // 128
    float* s_red   = s_w + 128;        // 32 (4 used)

    const int tid = threadIdx.x;
    const int ray = blockIdx.x;

    // ---- stage all MLP weights into shared memory (plain fp32) ----
    for (int i = tid; i < 2048; i += 128) W[OFF_WS0 + i] = ws0[i];
    for (int i = tid; i < 4096; i += 128) W[OFF_WS1 + i] = ws1[i];
    for (int i = tid; i < 1024; i += 128) W[OFF_WS2 + i] = ws2[i];
    for (int i = tid; i < 1984; i += 128) W[OFF_WC0 + i] = wc0[i];
    for (int i = tid; i < 4096; i += 128) W[OFF_WC1 + i] = wc1[i];
    for (int i = tid; i < 4096; i += 128) W[OFF_WC2 + i] = wc2[i];
    for (int i = tid; i < 192;  i += 128) W[OFF_WC3 + i] = wc3[i];
    __syncthreads();

    // ---- ray / sample setup ----
    const float ox = rays[ray * 6 + 0];
    const float oy = rays[ray * 6 + 1];
    const float oz = rays[ray * 6 + 2];
    const float dx = rays[ray * 6 + 3];
    const float dy = rays[ray * 6 + 4];
    const float dz = rays[ray * 6 + 5];

    const float step = 4.0f / 127.0f;
    const float z     = __fadd_rn(2.0f, __fmul_rn(step, (float)tid));
    const float znext = __fadd_rn(2.0f, __fmul_rn(step, (float)(tid + 1)));

    const float px = __fadd_rn(ox, __fmul_rn(dx, z));
    const float py = __fadd_rn(oy, __fmul_rn(dy, z));
    const float pz = __fadd_rn(oz, __fmul_rn(dz, z));

    // clip + keep mask
    const float cx = fminf(fmaxf(px, -1.5f), 1.5f);
    const float cy = fminf(fmaxf(py, -1.5f), 1.5f);
    const float cz = fminf(fmaxf(pz, -1.5f), 1.5f);
    const bool keep = (px == cx) && (py == cy) && (pz == cz);

    // ---- multi-resolution hash encoding (32 features) ----
    float featl[32];                     // local mem (dynamic-indexed later)
    #pragma unroll 1
    for (int l = 0; l < 16; l++) {
        const float res  = c_res[l];
        const float grid = 3.0f / res;

        float tx = (cx - (-1.5f)) / grid;
        float ty = (cy - (-1.5f)) / grid;
        float tz = (cz - (-1.5f)) / grid;
        float fbx = floorf(tx), fby = floorf(ty), fbz = floorf(tz);
        float vmx = fbx * grid + (-1.5f);
        float vmy = fby * grid + (-1.5f);
        float vmz = fbz * grid + (-1.5f);
        float wx = (cx - vmx) / grid;
        float wy = (cy - vmy) / grid;
        float wz = (cz - vmz) / grid;

        unsigned bx = (unsigned)(int)fbx;
        unsigned by = (unsigned)(int)fby;
        unsigned bz = (unsigned)(int)fbz;

        unsigned hx0 = bx;
        unsigned hx1 = bx + 1u;
        unsigned hy0 = by * 2654435761u;
        unsigned hy1 = (by + 1u) * 2654435761u;
        unsigned hz0 = bz * 805459861u;
        unsigned hz1 = (bz + 1u) * 805459861u;

        const float2* tab = reinterpret_cast<const float2*>(tables) + ((size_t)l << 19);
        float2 e000 = __ldg(&tab[(hx0 ^ hy0 ^ hz0) & TMASK]);
        float2 e001 = __ldg(&tab[(hx0 ^ hy0 ^ hz1) & TMASK]);
        float2 e010 = __ldg(&tab[(hx0 ^ hy1 ^ hz0) & TMASK]);
        float2 e011 = __ldg(&tab[(hx0 ^ hy1 ^ hz1) & TMASK]);
        float2 e100 = __ldg(&tab[(hx1 ^ hy0 ^ hz0) & TMASK]);
        float2 e101 = __ldg(&tab[(hx1 ^ hy0 ^ hz1) & TMASK]);
        float2 e110 = __ldg(&tab[(hx1 ^ hy1 ^ hz0) & TMASK]);
        float2 e111 = __ldg(&tab[(hx1 ^ hy1 ^ hz1) & TMASK]);

        const float u0 = 1.0f - wx, u1 = 1.0f - wy, u2 = 1.0f - wz;
        float c00a = e000.x * u0 + e100.x * wx, c00b = e000.y * u0 + e100.y * wx;
        float c01a = e001.x * u0 + e101.x * wx, c01b = e001.y * u0 + e101.y * wx;
        float c10a = e010.x * u0 + e110.x * wx, c10b = e010.y * u0 + e110.y * wx;
        float c11a = e011.x * u0 + e111.x * wx, c11b = e011.y * u0 + e111.y * wx;
        float c0a = c00a * u1 + c10a * wy, c0b = c00b * u1 + c10b * wy;
        float c1a = c01a * u1 + c11a * wy, c1b = c01b * u1 + c11b * wy;
        featl[l * 2 + 0] = c0a * u2 + c1a * wz;
        featl[l * 2 + 1] = c0b * u2 + c1b * wz;
    }

    // ---- sigma MLP: 32 -> 64 -> 64 -> 16 (fp32) ----
    float acc[64];
    #pragma unroll
    for (int j = 0; j < 64; j++) acc[j] = 0.0f;
    #pragma unroll 1
    for (int i = 0; i < 32; i++) {
        const float v = featl[i];
        const float4* wr = reinterpret_cast<const float4*>(W + OFF_WS0 + i * 64);
        #pragma unroll
        for (int q = 0; q < 16; q++) {
            float4 ww = wr[q];
            acc[4*q+0] = fmaf(v, ww.x, acc[4*q+0]);
            acc[4*q+1] = fmaf(v, ww.y, acc[4*q+1]);
            acc[4*q+2] = fmaf(v, ww.z, acc[4*q+2]);
            acc[4*q+3] = fmaf(v, ww.w, acc[4*q+3]);
        }
    }
    float actl[64];                      // local mem
    #pragma unroll
    for (int j = 0; j < 64; j++) actl[j] = fmaxf(acc[j], 0.0f);

    #pragma unroll
    for (int j = 0; j < 64; j++) acc[j] = 0.0f;
    #pragma unroll 1
    for (int i = 0; i < 64; i++) {
        const float v = actl[i];
        const float4* wr = reinterpret_cast<const float4*>(W + OFF_WS1 + i * 64);
        #pragma unroll
        for (int q = 0; q < 16; q++) {
            float4 ww = wr[q];
            acc[4*q+0] = fmaf(v, ww.x, acc[4*q+0]);
            acc[4*q+1] = fmaf(v, ww.y, acc[4*q+1]);
            acc[4*q+2] = fmaf(v, ww.z, acc[4*q+2]);
            acc[4*q+3] = fmaf(v, ww.w, acc[4*q+3]);
        }
    }
    #pragma unroll
    for (int j = 0; j < 64; j++) actl[j] = fmaxf(acc[j], 0.0f);

    float h3[16];
    #pragma unroll
    for (int j = 0; j < 16; j++) h3[j] = 0.0f;
    #pragma unroll 1
    for (int i = 0; i < 64; i++) {
        const float v = actl[i];
        const float4* wr = reinterpret_cast<const float4*>(W + OFF_WS2 + i * 16);
        #pragma unroll
        for (int q = 0; q < 4; q++) {
            float4 ww = wr[q];
            h3[4*q+0] = fmaf(v, ww.x, h3[4*q+0]);
            h3[4*q+1] = fmaf(v, ww.y, h3[4*q+1]);
            h3[4*q+2] = fmaf(v, ww.z, h3[4*q+2]);
            h3[4*q+3] = fmaf(v, ww.w, h3[4*q+3]);
        }
    }
    float sigma = h3[0];

    // ---- SH degree-4 encoding of direction + geo features -> color input (31) ----
    float cin[31];                       // local mem
    {
        const float x = dx, y = dy, zc = dz;
        const float xx = x * x, yy = y * y, zz = zc * zc;
        const float xy = x * y, yz = y * zc, xz = x * zc;
        cin[0]  = 0.28209479177387814f;
        cin[1]  = -0.4886025119029199f * y;
        cin[2]  = 0.4886025119029199f * zc;
        cin[3]  = -0.4886025119029199f * x;
        cin[4]  = 1.0925484305920792f * xy;
        cin[5]  = -1.0925484305920792f * yz;
        cin[6]  = 0.31539156525252005f * (2.0f * zz - xx - yy);
        cin[7]  = -1.0925484305920792f * xz;
        cin[8]  = 0.5462742152960396f * (xx - yy);
        cin[9]  = -0.5900435899266435f * y * (3.0f * xx - yy);
        cin[10] = 2.890611442640554f * xy * zc;
        cin[11] = -0.4570457994644658f * y * (4.0f * zz - xx - yy);
        cin[12] = 0.3731763325901154f * zc * (2.0f * zz - 3.0f * xx - 3.0f * yy);
        cin[13] = -0.4570457994644658f * x * (4.0f * zz - xx - yy);
        cin[14] = 1.445305721320277f * zc * (xx - yy);
        cin[15] = -0.5900435899266435f * x * (xx - 3.0f * yy);
        #pragma unroll
        for (int j = 0; j < 15; j++) cin[16 + j] = h3[1 + j];
    }

    // ---- color MLP: 31 -> 64 -> 64 -> 64 -> 3 (fp32) ----
    #pragma unroll
    for (int j = 0; j < 64; j++) acc[j] = 0.0f;
    #pragma unroll 1
    for (int i = 0; i < 31; i++) {
        const float v = cin[i];
        const float4* wr = reinterpret_cast<const float4*>(W + OFF_WC0 + i * 64);
        #pragma unroll
        for (int q = 0; q < 16; q++) {
            float4 ww = wr[q];
            acc[4*q+0] = fmaf(v, ww.x, acc[4*q+0]);
            acc[4*q+1] = fmaf(v, ww.y, acc[4*q+1]);
            acc[4*q+2] = fmaf(v, ww.z, acc[4*q+2]);
            acc[4*q+3] = fmaf(v, ww.w, acc[4*q+3]);
        }
    }
    #pragma unroll
    for (int j = 0; j < 64; j++) actl[j] = fmaxf(acc[j], 0.0f);

    #pragma unroll
    for (int j = 0; j < 64; j++) acc[j] = 0.0f;
    #pragma unroll 1
    for (int i = 0; i < 64; i++) {
        const float v = actl[i];
        const float4* wr = reinterpret_cast<const float4*>(W + OFF_WC1 + i * 64);
        #pragma unroll
        for (int q = 0; q < 16; q++) {
            float4 ww = wr[q];
            acc[4*q+0] = fmaf(v, ww.x, acc[4*q+0]);
            acc[4*q+1] = fmaf(v, ww.y, acc[4*q+1]);
            acc[4*q+2] = fmaf(v, ww.z, acc[4*q+2]);
            acc[4*q+3] = fmaf(v, ww.w, acc[4*q+3]);
        }
    }
    #pragma unroll
    for (int j = 0; j < 64; j++) actl[j] = fmaxf(acc[j], 0.0f);

    #pragma unroll
    for (int j = 0; j < 64; j++) acc[j] = 0.0f;
    #pragma unroll 1
    for (int i = 0; i < 64; i++) {
        const float v = actl[i];
        const float4* wr = reinterpret_cast<const float4*>(W + OFF_WC2 + i * 64);
        #pragma unroll
        for (int q = 0; q < 16; q++) {
            float4 ww = wr[q];
            acc[4*q+0] = fmaf(v, ww.x, acc[4*q+0]);
            acc[4*q+1] = fmaf(v, ww.y, acc[4*q+1]);
            acc[4*q+2] = fmaf(v, ww.z, acc[4*q+2]);
            acc[4*q+3] = fmaf(v, ww.w, acc[4*q+3]);
        }
    }
    #pragma unroll
    for (int j = 0; j < 64; j++) actl[j] = fmaxf(acc[j], 0.0f);

    float col0 = 0.0f, col1 = 0.0f, col2 = 0.0f;
    #pragma unroll 1
    for (int i = 0; i < 64; i++) {
        const float v = actl[i];
        const float* wr = W + OFF_WC3 + i * 3;
        col0 = fmaf(v, wr[0], col0);
        col1 = fmaf(v, wr[1], col1);
        col2 = fmaf(v, wr[2], col2);
    }

    // ---- compositing: reference-faithful quantized alpha ----
    // Reference: alpha = 1 - fl32(exp(-x)). Its exp is effectively correctly
    // rounded near 1; reproduce via fp64 exp + float cast (correct rounding),
    // then exact Sterbenz subtract. This matches the reference's alpha BITS.
    if (!keep) sigma = 0.0f;
    const float n2   = __fadd_rn(__fadd_rn(__fmul_rn(dx, dx), __fmul_rn(dy, dy)),
                                 __fmul_rn(dz, dz));
    const float norm = __fsqrt_rn(n2);
    const float dz_s = __fsub_rn(znext, z);
    const float dist = (tid == 127) ? __fmul_rn(1e10f, norm) : __fmul_rn(dz_s, norm);
    const float xarg = __fmul_rn(fmaxf(sigma, 0.0f), dist);
    const float e32  = (float)__nv_exp(-(double)xarg);   // correctly-rounded fp32 exp
    const float alpha = __fsub_rn(1.0f, e32);

    s_alpha[tid] = alpha;
    __syncthreads();
    if (tid == 0) {
        float t = 1.0f;
        #pragma unroll 1
        for (int i = 0; i < 128; i++) {
            float a = s_alpha[i];
            s_w[i] = __fmul_rn(a, t);
            t = __fmul_rn(t, __fadd_rn(__fsub_rn(1.0f, a), 1e-10f));
        }
    }
    __syncthreads();
    const float wgt = s_w[tid];

    const float sc0 = 1.0f / (1.0f + __nv_expf(-col0));
    const float sc1 = 1.0f / (1.0f + __nv_expf(-col1));
    const float sc2 = 1.0f / (1.0f + __nv_expf(-col2));

    const float r0 = block_reduce_128(wgt * sc0, s_red);
    const float r1 = block_reduce_128(wgt * sc1, s_red);
    const float r2 = block_reduce_128(wgt * sc2, s_red);
    const float rd = block_reduce_128(wgt * z, s_red);
    const float sw = block_reduce_128(wgt, s_red);

    const float plast = __fadd_rn(__fsub_rn(1.0f, sw), 1e-6f);
    const float S = __fadd_rn(sw, plast);
    float p = wgt / S;
    float ent = -p * __nv_logf(fmaxf(p, 1e-37f));
    if (tid == 0) {
        float pl = plast / S;
        ent += -pl * __nv_logf(fmaxf(pl, 1e-37f));
    }
    const float rent = block_reduce_128(ent, s_red);

    if (tid == 0) {
        out[ray * 3 + 0] = r0;
        out[ray * 3 + 1] = r1;
        out[ray * 3 + 2] = r2;
        out[NRAYS * 3 + ray] = rd;
        out[NRAYS * 4 + ray] = rent;
    }
}

extern "C" void kernel_launch(void* const* d_in, const int* in_sizes, int n_in,
                              void* d_out, int out_size) {
    const float* rays   = (const float*)d_in[0];
    const float* tables = (const float*)d_in[1];
    const float* ws0    = (const float*)d_in[2];
    const float* ws1    = (const float*)d_in[3];
    const float* ws2    = (const float*)d_in[4];
    const float* wc0    = (const float*)d_in[5];
    const float* wc1    = (const float*)d_in[6];
    const float* wc2    = (const float*)d_in[7];
    const float* wc3    = (const float*)d_in[8];
    float* out = (float*)d_out;

    cudaFuncSetAttribute(nerf_fused, cudaFuncAttributeMaxDynamicSharedMemorySize, SMEM_BYTES);
    nerf_fused<<<NRAYS, 128, SMEM_BYTES>>>(rays, tables, ws0, ws1, ws2,
                                           wc0, wc1, wc2, wc3, out);
}

// round 10
// speedup vs baseline: 1.4000x; 1.4000x over previous
#include <cuda_runtime.h>
#include <math.h>

#define NRAYS   16384
#define NSAMP   128
#define TMASK   ((1u << 19) - 1u)
#define RPB     4                 // rays per block
#define NTHR    (128 * RPB)

extern "C" {
__device__ float  __nv_expf(float);
__device__ float  __nv_logf(float);
__device__ double __nv_exp(double);
}

// shared-memory weight offsets (in floats)
#define OFF_WS0 0        // 32x64
#define OFF_WS1 2048     // 64x64
#define OFF_WS2 6144     // 64x16
#define OFF_WC0 7168     // 31x64
#define OFF_WC1 9152     // 64x64
#define OFF_WC2 13248    // 64x64
#define OFF_WC3 17344    // 64x3
#define WTOT    17536

#define RAYBUF  288               // per-ray: alpha[128] w[128] red[32]
#define SMEM_FLOATS (WTOT + RPB * RAYBUF)
#define SMEM_BYTES  (SMEM_FLOATS * 4)

__constant__ float c_res[16] = {16.f, 20.f, 25.f, 32.f, 40.f, 50.f, 64.f, 80.f,
                                101.f, 128.f, 161.f, 203.f, 256.f, 322.f, 406.f, 512.f};

// Packed dual-FMA: two independent IEEE fp32 FMAs (bit-identical to scalar).
__device__ __forceinline__ unsigned long long ffma2(unsigned long long a,
                                                    unsigned long long b,
                                                    unsigned long long c) {
    unsigned long long d;
    asm("fma.rn.f32x2 %0, %1, %2, %3;" : "=l"(d) : "l"(a), "l"(b), "l"(c));
    return d;
}
__device__ __forceinline__ unsigned long long pack2(float v) {
    unsigned long long d;
    unsigned r = __float_as_uint(v);
    asm("mov.b64 %0, {%1, %2};" : "=l"(d) : "r"(r), "r"(r));
    return d;
}
__device__ __forceinline__ void unpack2(unsigned long long p, float& lo, float& hi) {
    asm("mov.b64 {%0, %1}, %2;" : "=f"(lo), "=f"(hi) : "l"(p));
}

// 64-output layer in two 32-output half-passes (acc = 16 x b64 = 32 regs).
// Bit-identical accumulation order per output vs scalar version.
__device__ __forceinline__ void layer64(const float* __restrict__ Wb, int n_in,
                                        const float* __restrict__ in,
                                        float* __restrict__ outv, bool relu) {
    #pragma unroll 1
    for (int h = 0; h < 2; h++) {
        unsigned long long acc2[16];
        #pragma unroll
        for (int k = 0; k < 16; k++) acc2[k] = 0ULL;
        #pragma unroll 1
        for (int i = 0; i < n_in; i++) {
            const unsigned long long vv = pack2(in[i]);
            const ulonglong2* wr = reinterpret_cast<const ulonglong2*>(Wb + i * 64 + h * 32);
            #pragma unroll
            for (int q = 0; q < 8; q++) {
                ulonglong2 w2 = wr[q];
                acc2[2*q]   = ffma2(vv, w2.x, acc2[2*q]);
                acc2[2*q+1] = ffma2(vv, w2.y, acc2[2*q+1]);
            }
        }
        #pragma unroll
        for (int k = 0; k < 16; k++) {
            float lo, hi;
            unpack2(acc2[k], lo, hi);
            if (relu) { lo = fmaxf(lo, 0.0f); hi = fmaxf(hi, 0.0f); }
            outv[h * 32 + 2*k]     = lo;
            outv[h * 32 + 2*k + 1] = hi;
        }
    }
}

__global__ void __launch_bounds__(NTHR, 2)
nerf_fused(const float* __restrict__ rays,
           const float* __restrict__ tables,
           const float* __restrict__ ws0, const float* __restrict__ ws1,
           const float* __restrict__ ws2,
           const float* __restrict__ wc0, const float* __restrict__ wc1,
           const float* __restrict__ wc2, const float* __restrict__ wc3,
           float* __restrict__ out)
{
    extern __shared__ float sm[];
    float* W = sm;

    const int tid = threadIdx.x;
    const int r   = tid >> 7;         // ray slot in block
    const int s   = tid & 127;        // sample index
    const int ray = blockIdx.x * RPB + r;

    float* s_alpha = sm + WTOT + r * RAYBUF;
    float* s_w     = s_alpha + 128;
    float* s_red   = s_w + 128;

    // ---- stage all MLP weights (plain fp32) ----
    for (int i = tid; i < 2048; i += NTHR) W[OFF_WS0 + i] = ws0[i];
    for (int i = tid; i < 4096; i += NTHR) W[OFF_WS1 + i] = ws1[i];
    for (int i = tid; i < 1024; i += NTHR) W[OFF_WS2 + i] = ws2[i];
    for (int i = tid; i < 1984; i += NTHR) W[OFF_WC0 + i] = wc0[i];
    for (int i = tid; i < 4096; i += NTHR) W[OFF_WC1 + i] = wc1[i];
    for (int i = tid; i < 4096; i += NTHR) W[OFF_WC2 + i] = wc2[i];
    for (int i = tid; i < 192;  i += NTHR) W[OFF_WC3 + i] = wc3[i];
    __syncthreads();

    // ---- ray / sample setup ----
    const float ox = rays[ray * 6 + 0];
    const float oy = rays[ray * 6 + 1];
    const float oz = rays[ray * 6 + 2];
    const float dx = rays[ray * 6 + 3];
    const float dy = rays[ray * 6 + 4];
    const float dz = rays[ray * 6 + 5];

    const float step = 4.0f / 127.0f;
    const float z     = __fadd_rn(2.0f, __fmul_rn(step, (float)s));
    const float znext = __fadd_rn(2.0f, __fmul_rn(step, (float)(s + 1)));

    const float px = __fadd_rn(ox, __fmul_rn(dx, z));
    const float py = __fadd_rn(oy, __fmul_rn(dy, z));
    const float pz = __fadd_rn(oz, __fmul_rn(dz, z));

    const float cx = fminf(fmaxf(px, -1.5f), 1.5f);
    const float cy = fminf(fmaxf(py, -1.5f), 1.5f);
    const float cz = fminf(fmaxf(pz, -1.5f), 1.5f);
    const bool keep = (px == cx) && (py == cy) && (pz == cz);

    // ---- multi-resolution hash encoding ----
    float featl[32];
    #pragma unroll 1
    for (int l = 0; l < 16; l++) {
        const float res  = c_res[l];
        const float grid = 3.0f / res;

        float tx = (cx - (-1.5f)) / grid;
        float ty = (cy - (-1.5f)) / grid;
        float tz = (cz - (-1.5f)) / grid;
        float fbx = floorf(tx), fby = floorf(ty), fbz = floorf(tz);
        float vmx = fbx * grid + (-1.5f);
        float vmy = fby * grid + (-1.5f);
        float vmz = fbz * grid + (-1.5f);
        float wx = (cx - vmx) / grid;
        float wy = (cy - vmy) / grid;
        float wz = (cz - vmz) / grid;

        unsigned bx = (unsigned)(int)fbx;
        unsigned by = (unsigned)(int)fby;
        unsigned bz = (unsigned)(int)fbz;

        unsigned hx0 = bx, hx1 = bx + 1u;
        unsigned hy0 = by * 2654435761u, hy1 = (by + 1u) * 2654435761u;
        unsigned hz0 = bz * 805459861u,  hz1 = (bz + 1u) * 805459861u;

        const float2* tab = reinterpret_cast<const float2*>(tables) + ((size_t)l << 19);
        float2 e000 = __ldg(&tab[(hx0 ^ hy0 ^ hz0) & TMASK]);
        float2 e001 = __ldg(&tab[(hx0 ^ hy0 ^ hz1) & TMASK]);
        float2 e010 = __ldg(&tab[(hx0 ^ hy1 ^ hz0) & TMASK]);
        float2 e011 = __ldg(&tab[(hx0 ^ hy1 ^ hz1) & TMASK]);
        float2 e100 = __ldg(&tab[(hx1 ^ hy0 ^ hz0) & TMASK]);
        float2 e101 = __ldg(&tab[(hx1 ^ hy0 ^ hz1) & TMASK]);
        float2 e110 = __ldg(&tab[(hx1 ^ hy1 ^ hz0) & TMASK]);
        float2 e111 = __ldg(&tab[(hx1 ^ hy1 ^ hz1) & TMASK]);

        const float u0 = 1.0f - wx, u1 = 1.0f - wy, u2 = 1.0f - wz;
        float c00a = e000.x * u0 + e100.x * wx, c00b = e000.y * u0 + e100.y * wx;
        float c01a = e001.x * u0 + e101.x * wx, c01b = e001.y * u0 + e101.y * wx;
        float c10a = e010.x * u0 + e110.x * wx, c10b = e010.y * u0 + e110.y * wx;
        float c11a = e011.x * u0 + e111.x * wx, c11b = e011.y * u0 + e111.y * wx;
        float c0a = c00a * u1 + c10a * wy, c0b = c00b * u1 + c10b * wy;
        float c1a = c01a * u1 + c11a * wy, c1b = c01b * u1 + c11b * wy;
        featl[l * 2 + 0] = c0a * u2 + c1a * wz;
        featl[l * 2 + 1] = c0b * u2 + c1b * wz;
    }

    // ---- sigma MLP: 32 -> 64 -> 64 -> 16 ----
    float actl[64];
    layer64(W + OFF_WS0, 32, featl, actl, true);
    {
        float tmp[64];
        layer64(W + OFF_WS1, 64, actl, tmp, true);
        #pragma unroll
        for (int j = 0; j < 64; j++) actl[j] = tmp[j];
    }
    float h3[16];
    {   // 64 -> 16, single pass (acc = 8 x b64)
        unsigned long long acc2[8];
        #pragma unroll
        for (int k = 0; k < 8; k++) acc2[k] = 0ULL;
        #pragma unroll 1
        for (int i = 0; i < 64; i++) {
            const unsigned long long vv = pack2(actl[i]);
            const ulonglong2* wr = reinterpret_cast<const ulonglong2*>(W + OFF_WS2 + i * 16);
            #pragma unroll
            for (int q = 0; q < 4; q++) {
                ulonglong2 w2 = wr[q];
                acc2[2*q]   = ffma2(vv, w2.x, acc2[2*q]);
                acc2[2*q+1] = ffma2(vv, w2.y, acc2[2*q+1]);
            }
        }
        #pragma unroll
        for (int k = 0; k < 8; k++) unpack2(acc2[k], h3[2*k], h3[2*k+1]);
    }
    float sigma = h3[0];

    // ---- SH + geo -> color input (31) ----
    float cin[31];
    {
        const float x = dx, y = dy, zc = dz;
        const float xx = x * x, yy = y * y, zz = zc * zc;
        const float xy = x * y, yz = y * zc, xz = x * zc;
        cin[0]  = 0.28209479177387814f;
        cin[1]  = -0.4886025119029199f * y;
        cin[2]  = 0.4886025119029199f * zc;
        cin[3]  = -0.4886025119029199f * x;
        cin[4]  = 1.0925484305920792f * xy;
        cin[5]  = -1.0925484305920792f * yz;
        cin[6]  = 0.31539156525252005f * (2.0f * zz - xx - yy);
        cin[7]  = -1.0925484305920792f * xz;
        cin[8]  = 0.5462742152960396f * (xx - yy);
        cin[9]  = -0.5900435899266435f * y * (3.0f * xx - yy);
        cin[10] = 2.890611442640554f * xy * zc;
        cin[11] = -0.4570457994644658f * y * (4.0f * zz - xx - yy);
        cin[12] = 0.3731763325901154f * zc * (2.0f * zz - 3.0f * xx - 3.0f * yy);
        cin[13] = -0.4570457994644658f * x * (4.0f * zz - xx - yy);
        cin[14] = 1.445305721320277f * zc * (xx - yy);
        cin[15] = -0.5900435899266435f * x * (xx - 3.0f * yy);
        #pragma unroll
        for (int j = 0; j < 15; j++) cin[16 + j] = h3[1 + j];
    }

    // ---- color MLP: 31 -> 64 -> 64 -> 64 -> 3 ----
    layer64(W + OFF_WC0, 31, cin, actl, true);
    {
        float tmp[64];
        layer64(W + OFF_WC1, 64, actl, tmp, true);
        layer64(W + OFF_WC2, 64, tmp, actl, true);
    }
    float col0 = 0.0f, col1 = 0.0f, col2 = 0.0f;
    #pragma unroll 1
    for (int i = 0; i < 64; i++) {
        const float v = actl[i];
        const float* wr = W + OFF_WC3 + i * 3;
        col0 = fmaf(v, wr[0], col0);
        col1 = fmaf(v, wr[1], col1);
        col2 = fmaf(v, wr[2], col2);
    }

    // ---- compositing (bit-identical to R9) ----
    if (!keep) sigma = 0.0f;
    const float n2   = __fadd_rn(__fadd_rn(__fmul_rn(dx, dx), __fmul_rn(dy, dy)),
                                 __fmul_rn(dz, dz));
    const float norm = __fsqrt_rn(n2);
    const float dz_s = __fsub_rn(znext, z);
    const float dist = (s == 127) ? __fmul_rn(1e10f, norm) : __fmul_rn(dz_s, norm);
    const float xarg = __fmul_rn(fmaxf(sigma, 0.0f), dist);
    const float e32  = (float)__nv_exp(-(double)xarg);   // correctly-rounded fp32 exp
    const float alpha = __fsub_rn(1.0f, e32);

    s_alpha[s] = alpha;
    __syncthreads();
    if (s == 0) {
        float t = 1.0f;
        #pragma unroll 1
        for (int i = 0; i < 128; i++) {
            float a = s_alpha[i];
            s_w[i] = __fmul_rn(a, t);
            t = __fmul_rn(t, __fadd_rn(__fsub_rn(1.0f, a), 1e-10f));
        }
    }
    __syncthreads();
    const float wgt = s_w[s];

    const float sc0 = 1.0f / (1.0f + __nv_expf(-col0));
    const float sc1 = 1.0f / (1.0f + __nv_expf(-col1));
    const float sc2 = 1.0f / (1.0f + __nv_expf(-col2));

    // per-ray 128-thread reduction (same combine order as before)
    float vals[6];
    vals[0] = wgt * sc0; vals[1] = wgt * sc1; vals[2] = wgt * sc2;
    vals[3] = wgt * z;   vals[4] = wgt;
    float res[5];
    #pragma unroll 1
    for (int t = 0; t < 5; t++) {
        float v = vals[t];
        #pragma unroll
        for (int o = 16; o > 0; o >>= 1) v += __shfl_down_sync(0xffffffffu, v, o);
        __syncthreads();
        if ((s & 31) == 0) s_red[s >> 5] = v;
        __syncthreads();
        res[t] = (s_red[0] + s_red[1]) + (s_red[2] + s_red[3]);
    }
    const float sw = res[4];

    const float plast = __fadd_rn(__fsub_rn(1.0f, sw), 1e-6f);
    const float S = __fadd_rn(sw, plast);
    float p = wgt / S;
    float ent = -p * __nv_logf(fmaxf(p, 1e-37f));
    if (s == 0) {
        float pl = plast / S;
        ent += -pl * __nv_logf(fmaxf(pl, 1e-37f));
    }
    {
        float v = ent;
        #pragma unroll
        for (int o = 16; o > 0; o >>= 1) v += __shfl_down_sync(0xffffffffu, v, o);
        __syncthreads();
        if ((s & 31) == 0) s_red[s >> 5] = v;
        __syncthreads();
        if (s == 0) {
            float rent = (s_red[0] + s_red[1]) + (s_red[2] + s_red[3]);
            out[ray * 3 + 0] = res[0];
            out[ray * 3 + 1] = res[1];
            out[ray * 3 + 2] = res[2];
            out[NRAYS * 3 + ray] = res[3];
            out[NRAYS * 4 + ray] = rent;
        }
    }
}

extern "C" void kernel_launch(void* const* d_in, const int* in_sizes, int n_in,
                              void* d_out, int out_size) {
    const float* rays   = (const float*)d_in[0];
    const float* tables = (const float*)d_in[1];
    const float* ws0    = (const float*)d_in[2];
    const float* ws1    = (const float*)d_in[3];
    const float* ws2    = (const float*)d_in[4];
    const float* wc0    = (const float*)d_in[5];
    const float* wc1    = (const float*)d_in[6];
    const float* wc2    = (const float*)d_in[7];
    const float* wc3    = (const float*)d_in[8];
    float* out = (float*)d_out;

    cudaFuncSetAttribute(nerf_fused, cudaFuncAttributeMaxDynamicSharedMemorySize, SMEM_BYTES);
    nerf_fused<<<NRAYS / RPB, NTHR, SMEM_BYTES>>>(rays, tables, ws0, ws1, ws2,
                                                  wc0, wc1, wc2, wc3, out);
}